// round 5
// baseline (speedup 1.0000x reference)
#include <cuda_runtime.h>
#include <cuda_fp16.h>
#include <cstdint>

#define N_NODES 10000
#define N_EDGES 640000
#define D 128

#define NB 592            // 4 blocks/SM * 148 SMs -> all co-resident (152-SM GB300: even safer)
#define T  256
#define NTILES 1250       // gemm tiles of 8 nodes
#define NQ (N_EDGES / 4)  // 160000 edge-quads
#define S  4              // cursor shards per node
#define M  (N_NODES * S)  // 40000 counters
#define PER 160           // scan: counters per thread (160*256 = 40960 >= M)

// ---- allocation-free scratch ----------------------------------------------
__device__ __half             g_yh[N_NODES * D];  // y = x@W^T fp16 (2.5MB)
__device__ int                g_count[M];         // zero-init; scan re-zeroes
__device__ int                g_cursor[M];        // excl prefix -> incl after fill
__device__ unsigned long long g_epack[N_EDGES];   // (val<<32)|src permuted by dst
__device__ unsigned           g_bcnt[3];          // barrier counters (self-reset)
__device__ unsigned           g_bflag[3];         // barrier release flags (self-reset)

// ---------------------------------------------------------------------------
// Grid barrier i (used once per kernel execution). Up/down counting:
// counter and flag both return to 0 before the kernel exits.
// ---------------------------------------------------------------------------
__device__ __forceinline__ void gbar(int i) {
    __syncthreads();
    if (threadIdx.x == 0) {
        __threadfence();
        unsigned t = atomicAdd(&g_bcnt[i], 1u);
        if (t == NB - 1) {
            atomicExch(&g_bflag[i], 1u);
        } else {
            while (atomicAdd(&g_bflag[i], 0u) == 0u) __nanosleep(128);
        }
        unsigned d = atomicSub(&g_bcnt[i], 1u);
        if (d == 1u) atomicExch(&g_bflag[i], 0u);  // last out resets flag
        __threadfence();
    }
    __syncthreads();
}

__device__ __forceinline__ void accum8(float* acc, uint4 r, float v) {
    float2 f;
    f = __half22float2(*(const __half2*)&r.x); acc[0] += v * f.x; acc[1] += v * f.y;
    f = __half22float2(*(const __half2*)&r.y); acc[2] += v * f.x; acc[3] += v * f.y;
    f = __half22float2(*(const __half2*)&r.z); acc[4] += v * f.x; acc[5] += v * f.y;
    f = __half22float2(*(const __half2*)&r.w); acc[6] += v * f.x; acc[7] += v * f.y;
}

// ---------------------------------------------------------------------------
// ONE persistent kernel; 3 grid barriers; everything stays in L2.
// ---------------------------------------------------------------------------
__global__ void __launch_bounds__(T, 4) fused_kernel(
    const float* __restrict__ x, const float* __restrict__ W,
    const void* __restrict__ srcp, const void* __restrict__ dstp,
    const float* __restrict__ vals, const float* __restrict__ bias,
    float* __restrict__ out)
{
    __shared__ float4 xs[8][32];
    __shared__ int s_flag;
    __shared__ int wsum[8];

    const int t   = threadIdx.x;
    const int bid = blockIdx.x;
    const int lane = t & 31;
    const int w    = t >> 5;

    // ---- index dtype sniff (warp 0; int32 false-positive prob ~(1e-4)^32) --
    if (t < 32) {
        long long v = ((const long long*)srcp)[t];
        int ok = (v >= 0 && v < N_NODES);
        int all = __all_sync(0xFFFFFFFFu, ok);
        if (t == 0) s_flag = all;
    }
    __syncthreads();
    const int idx64 = s_flag;

    // ======================= Phase A: gemm + histogram ======================
    for (int tile = bid; tile < NTILES; tile += NB) {
        int n0 = tile * 8;
        {
            int n = t >> 5, c = t & 31;
            int node = n0 + n;
            xs[n][c] = (node < N_NODES) ? ((const float4*)x)[node * 32 + c]
                                        : make_float4(0.f, 0.f, 0.f, 0.f);
        }
        __syncthreads();
        int o = t & 127, g = t >> 7;
        float acc[4] = {0.f, 0.f, 0.f, 0.f};
        const float4* Wo = (const float4*)(W + o * D);
#pragma unroll 8
        for (int c = 0; c < 32; c++) {
            float4 ww = __ldg(&Wo[c]);
#pragma unroll
            for (int n = 0; n < 4; n++) {
                float4 xv = xs[g * 4 + n][c];
                acc[n] += ww.x * xv.x + ww.y * xv.y + ww.z * xv.z + ww.w * xv.w;
            }
        }
#pragma unroll
        for (int n = 0; n < 4; n++) {
            int node = n0 + g * 4 + n;
            if (node < N_NODES) g_yh[node * D + o] = __float2half(acc[n]);
        }
        __syncthreads();
    }

    for (int q = bid * T + t; q < NQ; q += NB * T) {
        int d0, d1, d2, d3;
        if (idx64) {
            const longlong2* p = (const longlong2*)dstp;
            longlong2 a = __ldg(&p[2 * q]);
            longlong2 c = __ldg(&p[2 * q + 1]);
            d0 = (int)a.x; d1 = (int)a.y; d2 = (int)c.x; d3 = (int)c.y;
        } else {
            int4 a = __ldg(&((const int4*)dstp)[q]);
            d0 = a.x; d1 = a.y; d2 = a.z; d3 = a.w;
        }
        // shard by edge position within quad -> matches fill's mapping
        asm volatile("red.global.add.s32 [%0], %1;" :: "l"(g_count + d0 * S + 0), "r"(1) : "memory");
        asm volatile("red.global.add.s32 [%0], %1;" :: "l"(g_count + d1 * S + 1), "r"(1) : "memory");
        asm volatile("red.global.add.s32 [%0], %1;" :: "l"(g_count + d2 * S + 2), "r"(1) : "memory");
        asm volatile("red.global.add.s32 [%0], %1;" :: "l"(g_count + d3 * S + 3), "r"(1) : "memory");
    }

    gbar(0);

    // ======================= Phase B: scan (block 0) ========================
    if (bid == 0) {
        int base = t * PER;
        int ssum = 0;
        for (int i = 0; i < PER; i++) {
            int idx = base + i;
            if (idx < M) ssum += g_count[idx];
        }
        int incl = ssum;
#pragma unroll
        for (int off = 1; off < 32; off <<= 1) {
            int nb2 = __shfl_up_sync(0xFFFFFFFFu, incl, off);
            if (lane >= off) incl += nb2;
        }
        if (lane == 31) wsum[w] = incl;
        __syncthreads();
        if (w == 0 && lane < 8) {
            int v = wsum[lane];
            int wi = v;
#pragma unroll
            for (int off = 1; off < 8; off <<= 1) {
                int nb2 = __shfl_up_sync(0x000000FFu, wi, off);
                if (lane >= off) wi += nb2;
            }
            wsum[lane] = wi;
        }
        __syncthreads();
        int run = incl - ssum + ((w > 0) ? wsum[w - 1] : 0);
        for (int i = 0; i < PER; i++) {
            int idx = base + i;
            if (idx < M) {
                int c = g_count[idx];
                g_cursor[idx] = run;
                g_count[idx] = 0;       // restore for next replay
                run += c;
            }
        }
    }

    gbar(1);

    // ======================= Phase C: fill ==================================
    for (int q = bid * T + t; q < NQ; q += NB * T) {
        int s[4], d[4];
        if (idx64) {
            const longlong2* ps = (const longlong2*)srcp;
            const longlong2* pd = (const longlong2*)dstp;
            longlong2 a = __ldg(&ps[2 * q]);
            longlong2 b2 = __ldg(&ps[2 * q + 1]);
            s[0] = (int)a.x; s[1] = (int)a.y; s[2] = (int)b2.x; s[3] = (int)b2.y;
            longlong2 cc = __ldg(&pd[2 * q]);
            longlong2 dd = __ldg(&pd[2 * q + 1]);
            d[0] = (int)cc.x; d[1] = (int)cc.y; d[2] = (int)dd.x; d[3] = (int)dd.y;
        } else {
            int4 a = __ldg(&((const int4*)srcp)[q]);
            s[0] = a.x; s[1] = a.y; s[2] = a.z; s[3] = a.w;
            int4 bb = __ldg(&((const int4*)dstp)[q]);
            d[0] = bb.x; d[1] = bb.y; d[2] = bb.z; d[3] = bb.w;
        }
        float4 v = __ldg(&((const float4*)vals)[q]);
        float vf[4] = {v.x, v.y, v.z, v.w};
#pragma unroll
        for (int i = 0; i < 4; i++) {
            int pos = atomicAdd(g_cursor + d[i] * S + i, 1);
            unsigned long long pk =
                (unsigned long long)(unsigned)s[i] |
                ((unsigned long long)__float_as_uint(vf[i]) << 32);
            g_epack[pos] = pk;
        }
    }

    gbar(2);

    // ======================= Phase D: aggregate =============================
    // One warp per node; node n's edges span [cursor[4n-1], cursor[4n+3])
    // (shards of a node are contiguous in scan order).
    {
        const int gw = (bid * T + t) >> 5;
        const int nwarps = NB * (T / 32);
        const int half = lane >> 4;
        const int c    = lane & 15;
        const uint4* yv = (const uint4*)g_yh;

        for (int n = gw; n < N_NODES; n += nwarps) {
            int start = (n == 0) ? 0 : __ldg(g_cursor + n * S - 1);
            int end   = __ldg(g_cursor + n * S + 3);

            float acc0[8] = {0,0,0,0,0,0,0,0};
            float acc1[8] = {0,0,0,0,0,0,0,0};

            int base = start;
            for (; base + 4 <= end; base += 4) {
                unsigned long long e0 = __ldg(g_epack + base + half);
                unsigned long long e1 = __ldg(g_epack + base + 2 + half);
                int   s0 = (int)(unsigned)e0;
                float v0 = __uint_as_float((unsigned)(e0 >> 32));
                int   s1 = (int)(unsigned)e1;
                float v1 = __uint_as_float((unsigned)(e1 >> 32));
                uint4 r0 = __ldg(&yv[s0 * 16 + c]);
                uint4 r1 = __ldg(&yv[s1 * 16 + c]);
                accum8(acc0, r0, v0);
                accum8(acc1, r1, v1);
            }
            for (; base < end; base += 2) {
                int i = base + half;
                bool act = (i < end);
                int ii = act ? i : base;
                unsigned long long e0 = __ldg(g_epack + ii);
                int   s0 = (int)(unsigned)e0;
                float v0 = act ? __uint_as_float((unsigned)(e0 >> 32)) : 0.f;
                uint4 r0 = __ldg(&yv[s0 * 16 + c]);
                accum8(acc0, r0, v0);
            }

#pragma unroll
            for (int k = 0; k < 8; k++) acc0[k] += acc1[k];
#pragma unroll
            for (int k = 0; k < 8; k++)
                acc0[k] += __shfl_xor_sync(0xFFFFFFFFu, acc0[k], 16);

            if (lane < 16) {
                float4 b0 = __ldg(&((const float4*)bias)[c * 2]);
                float4 b1 = __ldg(&((const float4*)bias)[c * 2 + 1]);
                float4 w0 = make_float4(acc0[0] + b0.x, acc0[1] + b0.y,
                                        acc0[2] + b0.z, acc0[3] + b0.w);
                float4 w1 = make_float4(acc0[4] + b1.x, acc0[5] + b1.y,
                                        acc0[6] + b1.z, acc0[7] + b1.w);
                ((float4*)out)[n * 32 + c * 2]     = w0;
                ((float4*)out)[n * 32 + c * 2 + 1] = w1;
            }
        }
    }
}

// ---------------------------------------------------------------------------
// Launch: ONE graph node.
// ---------------------------------------------------------------------------
extern "C" void kernel_launch(void* const* d_in, const int* in_sizes, int n_in,
                              void* d_out, int out_size)
{
    const float* x    = (const float*)d_in[0];
    const void*  srcp = d_in[1];
    const void*  dstp = d_in[2];
    const float* vals = (const float*)d_in[3];
    const float* W    = (const float*)d_in[4];
    const float* b    = (const float*)d_in[5];
    float* out = (float*)d_out;

    fused_kernel<<<NB, T>>>(x, W, srcp, dstp, vals, b, out);
}

// round 6
// speedup vs baseline: 1.8308x; 1.8308x over previous
#include <cuda_runtime.h>
#include <cuda_fp16.h>
#include <cstdint>

#define N_NODES 10000
#define N_EDGES 640000
#define D 128

#define GEMM_BLOCKS 313    // 32 nodes per block (313*32 = 10016)
#define HIST_BLOCKS 625    // 1024 edges per block
#define S 4                // cursor shards per node
#define M (N_NODES * S)    // 40000 counters
#define WT_STRIDE 132      // padded floats per k-row of transposed W
#define SMEM_DYN ((128 * WT_STRIDE + 32 * 128) * 4)  // 83968 B

// ---- allocation-free scratch ----------------------------------------------
__device__ __half             g_yh[N_NODES * D];  // y = x@W^T fp16 (2.5MB)
__device__ int                g_count[M];         // zero-init; scan re-zeroes
__device__ int                g_cursor[M];        // excl prefix -> incl after fill
__device__ unsigned long long g_epack[N_EDGES];   // (val<<32)|src permuted by dst

// Per-block index-dtype sniff (int32 false-positive prob ~(1e-4)^32).
__device__ __forceinline__ int block_sniff_idx64(const void* idxp, int t,
                                                 int* s_flag) {
    if (t < 32) {
        long long v = ((const long long*)idxp)[t];
        int ok = (v >= 0 && v < N_NODES);
        int all = __all_sync(0xFFFFFFFFu, ok);
        if (t == 0) *s_flag = all;
    }
    __syncthreads();
    return *s_flag;
}

// ---------------------------------------------------------------------------
// Fused: blocks [0,GEMM_BLOCKS) -> y = x@W^T (fp16, W transposed in smem,
// 4x4 register blocking); blocks [GEMM_BLOCKS,+HIST_BLOCKS) -> sharded
// dst histogram.
// ---------------------------------------------------------------------------
__global__ void __launch_bounds__(256) gemm_hist_kernel(
    const float* __restrict__ x, const float* __restrict__ W,
    const void* __restrict__ dstp)
{
    extern __shared__ float smem[];
    int t = threadIdx.x;

    if (blockIdx.x < GEMM_BLOCKS) {
        float* Wt = smem;                    // [128][WT_STRIDE]
        float* xs = smem + 128 * WT_STRIDE;  // [32][128]
        int n0 = blockIdx.x * 32;

        // Transpose W into smem: coalesced scalar LDG, 4-way-conflict STS.
        for (int i = t; i < 128 * 128; i += 256) {
            int o = i >> 7, k = i & 127;
            Wt[k * WT_STRIDE + o] = __ldg(&W[i]);
        }
        // Stage 32 x rows (coalesced float4).
        for (int i = t; i < 32 * 32; i += 256) {
            int n = i >> 5, c = i & 31;
            int node = n0 + n;
            float4 v = (node < N_NODES) ? __ldg(&((const float4*)x)[node * 32 + c])
                                        : make_float4(0.f, 0.f, 0.f, 0.f);
            *(float4*)(xs + n * 128 + c * 4) = v;
        }
        __syncthreads();

        int oc = t & 31;   // column group: cols [4oc, 4oc+4)
        int ng = t >> 5;   // node group: nodes [4ng, 4ng+4)
        const float* xr0 = xs + (ng * 4 + 0) * 128;
        const float* xr1 = xs + (ng * 4 + 1) * 128;
        const float* xr2 = xs + (ng * 4 + 2) * 128;
        const float* xr3 = xs + (ng * 4 + 3) * 128;

        float4 a0 = {0,0,0,0}, a1 = {0,0,0,0}, a2 = {0,0,0,0}, a3 = {0,0,0,0};
#pragma unroll 4
        for (int k = 0; k < 128; k++) {
            float4 w = *(const float4*)(Wt + k * WT_STRIDE + oc * 4);
            float x0 = xr0[k], x1 = xr1[k], x2 = xr2[k], x3 = xr3[k];
            a0.x += x0 * w.x; a0.y += x0 * w.y; a0.z += x0 * w.z; a0.w += x0 * w.w;
            a1.x += x1 * w.x; a1.y += x1 * w.y; a1.z += x1 * w.z; a1.w += x1 * w.w;
            a2.x += x2 * w.x; a2.y += x2 * w.y; a2.z += x2 * w.z; a2.w += x2 * w.w;
            a3.x += x3 * w.x; a3.y += x3 * w.y; a3.z += x3 * w.z; a3.w += x3 * w.w;
        }

        uint2* yo = (uint2*)g_yh;  // 4 halves per 8B; row = 32 uint2
        float4 av[4] = {a0, a1, a2, a3};
#pragma unroll
        for (int n = 0; n < 4; n++) {
            int node = n0 + ng * 4 + n;
            if (node < N_NODES) {
                __half2 h0 = __floats2half2_rn(av[n].x, av[n].y);
                __half2 h1 = __floats2half2_rn(av[n].z, av[n].w);
                uint2 pk;
                pk.x = *(unsigned*)&h0;
                pk.y = *(unsigned*)&h1;
                yo[node * 32 + oc] = pk;
            }
        }
    } else {
        __shared__ int s_flag;
        int idx64 = block_sniff_idx64(dstp, t, &s_flag);

        int hb = blockIdx.x - GEMM_BLOCKS;
        int q = hb * 256 + t;  // quad index

        int d0, d1, d2, d3;
        if (idx64) {
            const longlong2* p = (const longlong2*)dstp;
            longlong2 a = __ldg(&p[2 * q]);
            longlong2 c = __ldg(&p[2 * q + 1]);
            d0 = (int)a.x; d1 = (int)a.y; d2 = (int)c.x; d3 = (int)c.y;
        } else {
            int4 a = __ldg(&((const int4*)dstp)[q]);
            d0 = a.x; d1 = a.y; d2 = a.z; d3 = a.w;
        }
        asm volatile("red.global.add.s32 [%0], %1;" :: "l"(g_count + d0 * S + 0), "r"(1) : "memory");
        asm volatile("red.global.add.s32 [%0], %1;" :: "l"(g_count + d1 * S + 1), "r"(1) : "memory");
        asm volatile("red.global.add.s32 [%0], %1;" :: "l"(g_count + d2 * S + 2), "r"(1) : "memory");
        asm volatile("red.global.add.s32 [%0], %1;" :: "l"(g_count + d3 * S + 3), "r"(1) : "memory");
    }
}

// ---------------------------------------------------------------------------
// Shuffle-based exclusive scan over M=40000 counters (1024 thr x 40 each).
// Re-zeroes g_count for the next graph replay.
// ---------------------------------------------------------------------------
__global__ void __launch_bounds__(1024) scan_kernel() {
    __shared__ int warp_sums[32];
    const int PER = 40;  // 1024*40 = 40960 >= M
    int t = threadIdx.x;
    int lane = t & 31, w = t >> 5;
    int base = t * PER;

    int ssum = 0;
    for (int i = 0; i < PER; i++) {
        int idx = base + i;
        if (idx < M) ssum += g_count[idx];
    }

    int incl = ssum;
#pragma unroll
    for (int off = 1; off < 32; off <<= 1) {
        int nb = __shfl_up_sync(0xFFFFFFFFu, incl, off);
        if (lane >= off) incl += nb;
    }
    if (lane == 31) warp_sums[w] = incl;
    __syncthreads();
    if (w == 0) {
        int wi = warp_sums[lane];
#pragma unroll
        for (int off = 1; off < 32; off <<= 1) {
            int nb = __shfl_up_sync(0xFFFFFFFFu, wi, off);
            if (lane >= off) wi += nb;
        }
        warp_sums[lane] = wi;
    }
    __syncthreads();

    int run = incl - ssum + ((w > 0) ? warp_sums[w - 1] : 0);
    for (int i = 0; i < PER; i++) {
        int idx = base + i;
        if (idx < M) {
            int c = g_count[idx];
            g_cursor[idx] = run;
            g_count[idx] = 0;  // restore for replay
            run += c;
        }
    }
}

// ---------------------------------------------------------------------------
// Fill CSR payload into sharded slots: pos = atomicAdd(cursor[dst*4+i],1).
// After this, g_cursor[c] == inclusive end of cell c.
// ---------------------------------------------------------------------------
__global__ void __launch_bounds__(256) fill_kernel(
    const void* __restrict__ srcp, const void* __restrict__ dstp,
    const float* __restrict__ vals)
{
    __shared__ int s_flag;
    int t = threadIdx.x;
    int idx64 = block_sniff_idx64(srcp, t, &s_flag);

    int q = blockIdx.x * 256 + t;
    if (q * 4 >= N_EDGES) return;

    int s[4], d[4];
    if (idx64) {
        const longlong2* ps = (const longlong2*)srcp;
        const longlong2* pd = (const longlong2*)dstp;
        longlong2 a = __ldg(&ps[2 * q]);
        longlong2 b2 = __ldg(&ps[2 * q + 1]);
        s[0] = (int)a.x; s[1] = (int)a.y; s[2] = (int)b2.x; s[3] = (int)b2.y;
        longlong2 cc = __ldg(&pd[2 * q]);
        longlong2 dd = __ldg(&pd[2 * q + 1]);
        d[0] = (int)cc.x; d[1] = (int)cc.y; d[2] = (int)dd.x; d[3] = (int)dd.y;
    } else {
        int4 a = __ldg(&((const int4*)srcp)[q]);
        s[0] = a.x; s[1] = a.y; s[2] = a.z; s[3] = a.w;
        int4 bb = __ldg(&((const int4*)dstp)[q]);
        d[0] = bb.x; d[1] = bb.y; d[2] = bb.z; d[3] = bb.w;
    }
    float4 v = __ldg(&((const float4*)vals)[q]);
    float vf[4] = {v.x, v.y, v.z, v.w};

#pragma unroll
    for (int i = 0; i < 4; i++) {
        int pos = atomicAdd(g_cursor + d[i] * S + i, 1);
        unsigned long long pk =
            (unsigned long long)(unsigned)s[i] |
            ((unsigned long long)__float_as_uint(vf[i]) << 32);
        g_epack[pos] = pk;
    }
}

// ---------------------------------------------------------------------------
// Aggregate (R4 body): one warp per node, lanes 0-15 even edge / 16-31 odd,
// each lane one LDG.128 of 8 fp16 cols. Node n spans
// [cursor[4n-1], cursor[4n+3]) (shards contiguous in scan order).
// ---------------------------------------------------------------------------
__device__ __forceinline__ void accum8(float* acc, uint4 r, float v) {
    float2 f;
    f = __half22float2(*(const __half2*)&r.x); acc[0] += v * f.x; acc[1] += v * f.y;
    f = __half22float2(*(const __half2*)&r.y); acc[2] += v * f.x; acc[3] += v * f.y;
    f = __half22float2(*(const __half2*)&r.z); acc[4] += v * f.x; acc[5] += v * f.y;
    f = __half22float2(*(const __half2*)&r.w); acc[6] += v * f.x; acc[7] += v * f.y;
}

__global__ void __launch_bounds__(256) aggregate_kernel(
    const float* __restrict__ b, float* __restrict__ out)
{
    int warp = (blockIdx.x * blockDim.x + threadIdx.x) >> 5;
    int lane = threadIdx.x & 31;
    if (warp >= N_NODES) return;
    int n = warp;

    int start = (n == 0) ? 0 : __ldg(g_cursor + n * S - 1);
    int end   = __ldg(g_cursor + n * S + (S - 1));

    int half = lane >> 4;
    int c    = lane & 15;
    const uint4* yv = (const uint4*)g_yh;

    float acc0[8] = {0,0,0,0,0,0,0,0};
    float acc1[8] = {0,0,0,0,0,0,0,0};

    int base = start;
    for (; base + 4 <= end; base += 4) {
        unsigned long long e0 = __ldg(g_epack + base + half);
        unsigned long long e1 = __ldg(g_epack + base + 2 + half);
        int   s0 = (int)(unsigned)e0;
        float v0 = __uint_as_float((unsigned)(e0 >> 32));
        int   s1 = (int)(unsigned)e1;
        float v1 = __uint_as_float((unsigned)(e1 >> 32));
        uint4 r0 = __ldg(&yv[s0 * 16 + c]);
        uint4 r1 = __ldg(&yv[s1 * 16 + c]);
        accum8(acc0, r0, v0);
        accum8(acc1, r1, v1);
    }
    for (; base < end; base += 2) {
        int i = base + half;
        bool act = (i < end);
        int ii = act ? i : base;
        unsigned long long e0 = __ldg(g_epack + ii);
        int   s0 = (int)(unsigned)e0;
        float v0 = act ? __uint_as_float((unsigned)(e0 >> 32)) : 0.f;
        uint4 r0 = __ldg(&yv[s0 * 16 + c]);
        accum8(acc0, r0, v0);
    }

#pragma unroll
    for (int k = 0; k < 8; k++) acc0[k] += acc1[k];
#pragma unroll
    for (int k = 0; k < 8; k++)
        acc0[k] += __shfl_xor_sync(0xFFFFFFFFu, acc0[k], 16);

    if (lane < 16) {
        float4 b0 = __ldg(&((const float4*)b)[c * 2]);
        float4 b1 = __ldg(&((const float4*)b)[c * 2 + 1]);
        float4 w0 = make_float4(acc0[0] + b0.x, acc0[1] + b0.y,
                                acc0[2] + b0.z, acc0[3] + b0.w);
        float4 w1 = make_float4(acc0[4] + b1.x, acc0[5] + b1.y,
                                acc0[6] + b1.z, acc0[7] + b1.w);
        ((float4*)out)[n * 32 + c * 2]     = w0;
        ((float4*)out)[n * 32 + c * 2 + 1] = w1;
    }
}

// ---------------------------------------------------------------------------
// Launch: 4 graph nodes.
// ---------------------------------------------------------------------------
extern "C" void kernel_launch(void* const* d_in, const int* in_sizes, int n_in,
                              void* d_out, int out_size)
{
    const float* x    = (const float*)d_in[0];
    const void*  srcp = d_in[1];
    const void*  dstp = d_in[2];
    const float* vals = (const float*)d_in[3];
    const float* W    = (const float*)d_in[4];
    const float* b    = (const float*)d_in[5];
    float* out = (float*)d_out;

    cudaFuncSetAttribute(gemm_hist_kernel,
                         cudaFuncAttributeMaxDynamicSharedMemorySize, SMEM_DYN);

    gemm_hist_kernel<<<GEMM_BLOCKS + HIST_BLOCKS, 256, SMEM_DYN>>>(x, W, dstp);
    scan_kernel<<<1, 1024>>>();
    fill_kernel<<<(N_EDGES / 4 + 255) / 256, 256>>>(srcp, dstp, vals);
    aggregate_kernel<<<(N_NODES * 32 + 255) / 256, 256>>>(b, out);
}